// round 1
// baseline (speedup 1.0000x reference)
#include <cuda_runtime.h>

// Problem constants
#define N_   8
#define C_   64
#define H_   256
#define W_   256
#define G_   8
#define CPG_ 8              // channels per group
#define ROWS 8              // rows per block strip
#define CHUNKS (H_/ROWS)    // 32 strips per image
#define EPS_ 1e-5f
#define NTHREADS 256

// Scratch (no allocations allowed): per-(n,g,chunk) partial sums, and final stats.
__device__ float g_part[N_*G_*CHUNKS*2];
__device__ float g_stats[N_*G_*2];   // interleaved: mean, rstd

__device__ __forceinline__ float tanh_fast(float x) {
    float y;
    asm("tanh.approx.f32 %0, %1;" : "=f"(y) : "f"(x));
    return y;
}

// ---------------- Pass 1: depthwise conv + per-(n,g) sum / sumsq ----------------
__global__ __launch_bounds__(NTHREADS) void k_pass1(const float* __restrict__ x,
                                                    const float* __restrict__ wgt) {
    __shared__ float tile[ROWS+2][W_];
    __shared__ float red[8], red2[8];
    const int bid   = blockIdx.x;
    const int n     = bid / CHUNKS;
    const int chunk = bid % CHUNKS;
    const int h0    = chunk * ROWS;
    const int tid   = threadIdx.x;            // = column w
    const int lane  = tid & 31, wid = tid >> 5;
    const bool hasL = tid > 0, hasR = tid < W_-1;

    float gs = 0.f, gs2 = 0.f;
    for (int c = 0; c < C_; ++c) {
        const float* xc = x + (size_t)((n*C_ + c)*H_) * W_;
        #pragma unroll
        for (int r = 0; r < ROWS+2; ++r) {
            int h = h0 - 1 + r;
            tile[r][tid] = (h >= 0 && h < H_) ? xc[h*W_ + tid] : 0.f;
        }
        __syncthreads();

        float wk[9];
        #pragma unroll
        for (int i = 0; i < 9; ++i) wk[i] = wgt[i*C_ + c];  // weight layout [K,K,C]

        #pragma unroll
        for (int r = 0; r < ROWS; ++r) {
            float conv = 0.f;
            #pragma unroll
            for (int ky = 0; ky < 3; ++ky) {
                float a = hasL ? tile[r+ky][tid-1] : 0.f;
                float b =        tile[r+ky][tid];
                float d = hasR ? tile[r+ky][tid+1] : 0.f;
                conv = fmaf(a, wk[ky*3+0], conv);
                conv = fmaf(b, wk[ky*3+1], conv);
                conv = fmaf(d, wk[ky*3+2], conv);
            }
            gs  += conv;
            gs2  = fmaf(conv, conv, gs2);
        }
        __syncthreads();

        if ((c & (CPG_-1)) == (CPG_-1)) {          // flush one group's partial
            const int g = c >> 3;
            float s = gs, s2 = gs2;
            #pragma unroll
            for (int off = 16; off; off >>= 1) {
                s  += __shfl_down_sync(0xffffffffu, s,  off);
                s2 += __shfl_down_sync(0xffffffffu, s2, off);
            }
            if (lane == 0) { red[wid] = s; red2[wid] = s2; }
            __syncthreads();
            if (wid == 0) {
                s  = (lane < 8) ? red[lane]  : 0.f;
                s2 = (lane < 8) ? red2[lane] : 0.f;
                #pragma unroll
                for (int off = 4; off; off >>= 1) {
                    s  += __shfl_down_sync(0xffffffffu, s,  off);
                    s2 += __shfl_down_sync(0xffffffffu, s2, off);
                }
                if (lane == 0) {
                    const int idx = ((n*G_ + g)*CHUNKS + chunk)*2;
                    g_part[idx]   = s;
                    g_part[idx+1] = s2;
                }
            }
            gs = 0.f; gs2 = 0.f;
            __syncthreads();
        }
    }
}

// ---------------- Tiny reduce: partials -> mean, rstd (deterministic) ----------------
__global__ void k_reduce() {
    const int t = threadIdx.x;                  // 0..63 = n*G + g
    if (t < N_*G_) {
        float s = 0.f, s2 = 0.f;
        #pragma unroll
        for (int k = 0; k < CHUNKS; ++k) {
            s  += g_part[(t*CHUNKS + k)*2];
            s2 += g_part[(t*CHUNKS + k)*2 + 1];
        }
        const float inv = 1.0f / (float)(CPG_ * H_ * W_);
        const float m = s * inv;
        const float v = s2 * inv - m*m;
        g_stats[t*2]     = m;
        g_stats[t*2 + 1] = rsqrtf(v + EPS_);
    }
}

// ---------------- Pass 2: recompute conv, normalize, act, residual, LSE, broadcast ----------------
__global__ __launch_bounds__(NTHREADS) void k_pass2(const float* __restrict__ x,
                                                    const float* __restrict__ wgt,
                                                    float* __restrict__ out) {
    __shared__ float tile[ROWS+2][W_];
    __shared__ float s_mean[G_], s_rstd[G_];
    const int bid   = blockIdx.x;
    const int n     = bid / CHUNKS;
    const int chunk = bid % CHUNKS;
    const int h0    = chunk * ROWS;
    const int tid   = threadIdx.x;
    const bool hasL = tid > 0, hasR = tid < W_-1;

    if (tid < G_) {
        s_mean[tid] = g_stats[(n*G_ + tid)*2];
        s_rstd[tid] = g_stats[(n*G_ + tid)*2 + 1];
    }
    float acc[ROWS];
    #pragma unroll
    for (int r = 0; r < ROWS; ++r) acc[r] = 0.f;
    __syncthreads();

    for (int c = 0; c < C_; ++c) {
        const float* xc = x + (size_t)((n*C_ + c)*H_) * W_;
        #pragma unroll
        for (int r = 0; r < ROWS+2; ++r) {
            int h = h0 - 1 + r;
            tile[r][tid] = (h >= 0 && h < H_) ? xc[h*W_ + tid] : 0.f;
        }
        __syncthreads();

        float wk[9];
        #pragma unroll
        for (int i = 0; i < 9; ++i) wk[i] = wgt[i*C_ + c];
        const float mean = s_mean[c >> 3];
        const float rstd = s_rstd[c >> 3];

        #pragma unroll
        for (int r = 0; r < ROWS; ++r) {
            float conv = 0.f;
            #pragma unroll
            for (int ky = 0; ky < 3; ++ky) {
                float a = hasL ? tile[r+ky][tid-1] : 0.f;
                float b =        tile[r+ky][tid];
                float d = hasR ? tile[r+ky][tid+1] : 0.f;
                conv = fmaf(a, wk[ky*3+0], conv);
                conv = fmaf(b, wk[ky*3+1], conv);
                conv = fmaf(d, wk[ky*3+2], conv);
            }
            const float v = (conv - mean) * rstd;
            const float t = tanh_fast(v);
            // hardswish(t): t in (-1,1) => clip(t+3,0,6) == t+3 exactly
            const float xr = fmaf(t * (1.0f/6.0f), t + 3.0f, conv);
            acc[r] += __expf(xr);
        }
        __syncthreads();
    }

    // Stage per-pixel LSE into (now free) tile rows, then broadcast to all C channels.
    #pragma unroll
    for (int r = 0; r < ROWS; ++r) tile[r][tid] = __logf(acc[r]);
    __syncthreads();

    float4* o4 = (float4*)out;
    const int W4 = W_ / 4;                       // 64
    const int total = C_ * ROWS * W4;            // 32768 float4 per block
    for (int i = tid; i < total; i += NTHREADS) {
        const int w4 = i & (W4 - 1);
        const int r  = (i >> 6) & (ROWS - 1);
        const int c  = i >> 9;
        const float4 v = reinterpret_cast<float4*>(&tile[r][0])[w4];
        const size_t off = (size_t)((n*C_ + c)*H_ + h0 + r) * W4 + w4;
        __stcs(&o4[off], v);                     // streaming: don't evict x from L2
    }
}

extern "C" void kernel_launch(void* const* d_in, const int* in_sizes, int n_in,
                              void* d_out, int out_size) {
    const float* x   = (const float*)d_in[0];   // [8,64,256,256]
    const float* wgt = (const float*)d_in[1];   // [3,3,64]
    float* out = (float*)d_out;

    k_pass1 <<<N_*CHUNKS, NTHREADS>>>(x, wgt);
    k_reduce<<<1, 64>>>();
    k_pass2 <<<N_*CHUNKS, NTHREADS>>>(x, wgt, out);
}

// round 2
// speedup vs baseline: 1.9519x; 1.9519x over previous
#include <cuda_runtime.h>

#define N_   8
#define C_   64
#define H_   256
#define W_   256
#define G_   8
#define CPG_ 8               // channels per group
#define ROWS 8               // rows per block strip
#define CHUNKS (H_/ROWS)     // 32
#define EPS_ 1e-5f
#define NT   256
#define W4_  (W_/4)          // 64
#define HWQ  (H_*W_/4)       // 16384 quads per plane

// Scratch (static __device__ — no runtime allocation)
__device__ float g_part[N_*G_*CHUNKS*2];
__device__ float g_stats[N_*G_*2];                 // mean, rstd interleaved
__device__ float g_esum[(size_t)N_*G_*H_*W_];      // per-(n,g) sum of exp (16.8 MB)

__device__ __forceinline__ float tanh_fast(float x) {
    float y;
    asm("tanh.approx.f32 %0, %1;" : "=f"(y) : "f"(x));
    return y;
}

// ---------------- Pass 1: depthwise conv + per-(n,g,chunk) sum / sumsq ----------------
// grid: N*G*CHUNKS blocks; block owns one group (8 channels) over an 8-row strip.
__global__ __launch_bounds__(NT) void k_pass1(const float* __restrict__ x,
                                              const float* __restrict__ wgt) {
    __shared__ float4 tile4[(ROWS+2)*W4_];          // 10 rows x 256 cols
    __shared__ float  wsm[9][CPG_];
    __shared__ float  red[8], red2[8];
    float* tile = (float*)tile4;

    const int bid   = blockIdx.x;
    const int chunk = bid % CHUNKS;
    const int g     = (bid / CHUNKS) % G_;
    const int n     = bid / (CHUNKS * G_);
    const int h0    = chunk * ROWS;
    const int tid   = threadIdx.x;
    const int lane  = tid & 31, wid = tid >> 5;
    const bool hasL = tid > 0, hasR = tid < W_-1;

    if (tid < 9*CPG_) {
        const int k = tid / CPG_, cc = tid % CPG_;
        wsm[k][cc] = wgt[k*C_ + g*CPG_ + cc];
    }

    const float4* x4 = (const float4*)x;
    float gs = 0.f, gs2 = 0.f;

    for (int cc = 0; cc < CPG_; ++cc) {
        const int c = g*CPG_ + cc;
        const float4* xc4 = x4 + (size_t)(n*C_ + c) * HWQ;
        __syncthreads();                            // tile free from previous iter
        #pragma unroll
        for (int i = 0; i < 3; ++i) {
            const int idx = tid + i*NT;
            if (idx < (ROWS+2)*W4_) {
                const int r = idx >> 6, q = idx & (W4_-1);
                const int h = h0 - 1 + r;
                tile4[idx] = (h >= 0 && h < H_) ? __ldg(&xc4[h*W4_ + q])
                                                : make_float4(0.f,0.f,0.f,0.f);
            }
        }
        __syncthreads();

        float wk[9];
        #pragma unroll
        for (int k = 0; k < 9; ++k) wk[k] = wsm[k][cc];

        // register-rotating 3x3 window down the column tid
        float L0 = hasL ? tile[tid-1]     : 0.f;
        float M0 =        tile[tid];
        float R0 = hasR ? tile[tid+1]     : 0.f;
        float L1 = hasL ? tile[W_+tid-1]  : 0.f;
        float M1 =        tile[W_+tid];
        float R1 = hasR ? tile[W_+tid+1]  : 0.f;
        #pragma unroll
        for (int r = 0; r < ROWS; ++r) {
            const float* row2 = tile + (r+2)*W_;
            const float L2 = hasL ? row2[tid-1] : 0.f;
            const float M2 =        row2[tid];
            const float R2 = hasR ? row2[tid+1] : 0.f;
            float conv =        L0*wk[0];
            conv = fmaf(M0, wk[1], conv); conv = fmaf(R0, wk[2], conv);
            conv = fmaf(L1, wk[3], conv); conv = fmaf(M1, wk[4], conv);
            conv = fmaf(R1, wk[5], conv); conv = fmaf(L2, wk[6], conv);
            conv = fmaf(M2, wk[7], conv); conv = fmaf(R2, wk[8], conv);
            gs  += conv;
            gs2  = fmaf(conv, conv, gs2);
            L0=L1; M0=M1; R0=R1; L1=L2; M1=M2; R1=R2;
        }
    }

    // block reduction of (gs, gs2)
    #pragma unroll
    for (int off = 16; off; off >>= 1) {
        gs  += __shfl_down_sync(0xffffffffu, gs,  off);
        gs2 += __shfl_down_sync(0xffffffffu, gs2, off);
    }
    if (lane == 0) { red[wid] = gs; red2[wid] = gs2; }
    __syncthreads();
    if (wid == 0) {
        float s  = (lane < 8) ? red[lane]  : 0.f;
        float s2 = (lane < 8) ? red2[lane] : 0.f;
        #pragma unroll
        for (int off = 4; off; off >>= 1) {
            s  += __shfl_down_sync(0xffffffffu, s,  off);
            s2 += __shfl_down_sync(0xffffffffu, s2, off);
        }
        if (lane == 0) {
            const int idx = ((n*G_ + g)*CHUNKS + chunk)*2;
            g_part[idx]   = s;
            g_part[idx+1] = s2;
        }
    }
}

// ---------------- Tiny reduce: partials -> mean, rstd ----------------
__global__ void k_reduce() {
    const int t = threadIdx.x;                      // 0..63 = n*G + g
    if (t < N_*G_) {
        float s = 0.f, s2 = 0.f;
        #pragma unroll
        for (int k = 0; k < CHUNKS; ++k) {
            s  += g_part[(t*CHUNKS + k)*2];
            s2 += g_part[(t*CHUNKS + k)*2 + 1];
        }
        const float inv = 1.0f / (float)(CPG_*H_*W_);
        const float m = s * inv;
        const float v = s2 * inv - m*m;
        g_stats[t*2]   = m;
        g_stats[t*2+1] = rsqrtf(v + EPS_);
    }
}

// ---------------- Pass 2a: recompute conv, normalize, act, residual, partial exp-sum ----------------
__global__ __launch_bounds__(NT) void k_pass2a(const float* __restrict__ x,
                                               const float* __restrict__ wgt) {
    __shared__ float4 tile4[(ROWS+2)*W4_];
    __shared__ float  wsm[9][CPG_];
    float* tile = (float*)tile4;

    const int bid   = blockIdx.x;
    const int chunk = bid % CHUNKS;
    const int g     = (bid / CHUNKS) % G_;
    const int n     = bid / (CHUNKS * G_);
    const int h0    = chunk * ROWS;
    const int tid   = threadIdx.x;
    const bool hasL = tid > 0, hasR = tid < W_-1;

    if (tid < 9*CPG_) {
        const int k = tid / CPG_, cc = tid % CPG_;
        wsm[k][cc] = wgt[k*C_ + g*CPG_ + cc];
    }
    const float mean = g_stats[(n*G_ + g)*2];
    const float rstd = g_stats[(n*G_ + g)*2 + 1];

    float acc[ROWS];
    #pragma unroll
    for (int r = 0; r < ROWS; ++r) acc[r] = 0.f;

    const float4* x4 = (const float4*)x;

    for (int cc = 0; cc < CPG_; ++cc) {
        const int c = g*CPG_ + cc;
        const float4* xc4 = x4 + (size_t)(n*C_ + c) * HWQ;
        __syncthreads();
        #pragma unroll
        for (int i = 0; i < 3; ++i) {
            const int idx = tid + i*NT;
            if (idx < (ROWS+2)*W4_) {
                const int r = idx >> 6, q = idx & (W4_-1);
                const int h = h0 - 1 + r;
                tile4[idx] = (h >= 0 && h < H_) ? __ldg(&xc4[h*W4_ + q])
                                                : make_float4(0.f,0.f,0.f,0.f);
            }
        }
        __syncthreads();

        float wk[9];
        #pragma unroll
        for (int k = 0; k < 9; ++k) wk[k] = wsm[k][cc];

        float L0 = hasL ? tile[tid-1]     : 0.f;
        float M0 =        tile[tid];
        float R0 = hasR ? tile[tid+1]     : 0.f;
        float L1 = hasL ? tile[W_+tid-1]  : 0.f;
        float M1 =        tile[W_+tid];
        float R1 = hasR ? tile[W_+tid+1]  : 0.f;
        #pragma unroll
        for (int r = 0; r < ROWS; ++r) {
            const float* row2 = tile + (r+2)*W_;
            const float L2 = hasL ? row2[tid-1] : 0.f;
            const float M2 =        row2[tid];
            const float R2 = hasR ? row2[tid+1] : 0.f;
            float conv =        L0*wk[0];
            conv = fmaf(M0, wk[1], conv); conv = fmaf(R0, wk[2], conv);
            conv = fmaf(L1, wk[3], conv); conv = fmaf(M1, wk[4], conv);
            conv = fmaf(R1, wk[5], conv); conv = fmaf(L2, wk[6], conv);
            conv = fmaf(M2, wk[7], conv); conv = fmaf(R2, wk[8], conv);
            const float v = (conv - mean) * rstd;
            const float t = tanh_fast(v);
            // t in (-1,1) => clip(t+3,0,6) == t+3 exactly
            const float xr = fmaf(t * (1.0f/6.0f), t + 3.0f, conv);
            acc[r] += __expf(xr);
            L0=L1; M0=M1; R0=R1; L1=L2; M1=M2; R1=R2;
        }
    }

    // complete group sum for these pixels -> esum[n][g][h][w]
    float* es = g_esum + ((size_t)(n*G_ + g)*H_ + h0) * W_;
    #pragma unroll
    for (int r = 0; r < ROWS; ++r) es[r*W_ + tid] = acc[r];
}

// ---------------- Pass 2b: combine groups, log, broadcast to 64 channels ----------------
__global__ __launch_bounds__(NT) void k_pass2b(float* __restrict__ out) {
    const int p = blockIdx.x * NT + threadIdx.x;    // quad index, 0 .. N*HWQ-1
    const int n   = p >> 14;                        // / HWQ
    const int pix = p & (HWQ - 1);

    const float4* e4 = (const float4*)g_esum;
    const size_t ebase = (size_t)n*G_*HWQ + pix;
    float4 s = __ldg(&e4[ebase]);
    #pragma unroll
    for (int g = 1; g < G_; ++g) {
        const float4 v = __ldg(&e4[ebase + (size_t)g*HWQ]);
        s.x += v.x; s.y += v.y; s.z += v.z; s.w += v.w;
    }
    float4 L;
    L.x = __logf(s.x); L.y = __logf(s.y); L.z = __logf(s.z); L.w = __logf(s.w);

    float4* o4 = (float4*)out;
    const size_t obase = (size_t)n*C_*HWQ + pix;
    #pragma unroll
    for (int c = 0; c < C_; ++c) __stcs(&o4[obase + (size_t)c*HWQ], L);
}

extern "C" void kernel_launch(void* const* d_in, const int* in_sizes, int n_in,
                              void* d_out, int out_size) {
    const float* x   = (const float*)d_in[0];       // [8,64,256,256]
    const float* wgt = (const float*)d_in[1];       // [3,3,64]
    float* out = (float*)d_out;

    k_pass1 <<<N_*G_*CHUNKS, NT>>>(x, wgt);
    k_reduce<<<1, 64>>>();
    k_pass2a<<<N_*G_*CHUNKS, NT>>>(x, wgt);
    k_pass2b<<<(N_*HWQ)/NT, NT>>>(out);
}

// round 3
// speedup vs baseline: 2.1227x; 1.0875x over previous
#include <cuda_runtime.h>

#define N_   8
#define C_   64
#define H_   256
#define W_   256
#define G_   8
#define CPG_ 8               // channels per group
#define ROWS 16              // rows per block strip
#define TR   (ROWS+2)        // tile rows incl. halo
#define CHUNKS (H_/ROWS)     // 16
#define EPS_ 1e-5f
#define NT   256
#define W4_  (W_/4)          // 64
#define TQ   (TR*W4_)        // 1152 float4 per tile
#define HWQ  (H_*W_/4)       // 16384 quads per plane
#define CSPLIT 4             // channel split in pass2b
#define CHPB (C_/CSPLIT)     // 16 channels per pass2b block

// Static scratch (no runtime allocation)
__device__ float g_part[N_*G_*CHUNKS*2];
__device__ float g_stats[N_*G_*2];                 // mean, rstd interleaved
__device__ float g_esum[(size_t)N_*G_*H_*W_];      // per-(n,g) sum of exp (16.8 MB)

__device__ __forceinline__ float tanh_fast(float x) {
    float y;
    asm("tanh.approx.f32 %0, %1;" : "=f"(y) : "f"(x));
    return y;
}

// ---- tile staging helpers (double-buffered) ----
__device__ __forceinline__ void ldg_tile(float4 pre[5], const float4* xc4,
                                         int h0, int tid) {
    #pragma unroll
    for (int i = 0; i < 5; ++i) {
        const int idx = tid + i*NT;
        if (idx < TQ) {
            const int r = idx >> 6, q = idx & (W4_-1);
            const int h = h0 - 1 + r;
            pre[i] = (h >= 0 && h < H_) ? __ldg(&xc4[h*W4_ + q])
                                        : make_float4(0.f,0.f,0.f,0.f);
        }
    }
}
__device__ __forceinline__ void sts_tile(float4* buf, const float4 pre[5], int tid) {
    #pragma unroll
    for (int i = 0; i < 5; ++i) {
        const int idx = tid + i*NT;
        if (idx < TQ) buf[idx] = pre[i];
    }
}

// ---------------- Pass 1: depthwise conv + per-(n,g,chunk) sum / sumsq ----------------
__global__ __launch_bounds__(NT) void k_pass1(const float* __restrict__ x,
                                              const float* __restrict__ wgt) {
    __shared__ float4 buf[2][TQ];
    __shared__ float  wsm[9][CPG_];
    __shared__ float  red[8], red2[8];

    const int bid   = blockIdx.x;
    const int chunk = bid % CHUNKS;
    const int g     = (bid / CHUNKS) % G_;
    const int n     = bid / (CHUNKS * G_);
    const int h0    = chunk * ROWS;
    const int tid   = threadIdx.x;
    const int lane  = tid & 31, wid = tid >> 5;
    const bool hasL = tid > 0, hasR = tid < W_-1;

    if (tid < 9*CPG_) {
        const int k = tid / CPG_, cc = tid % CPG_;
        wsm[k][cc] = wgt[k*C_ + g*CPG_ + cc];
    }

    const float4* x4 = (const float4*)x;
    const size_t plane0 = (size_t)(n*C_ + g*CPG_) * HWQ;

    // prologue: load channel 0
    {
        float4 pre[5];
        ldg_tile(pre, x4 + plane0, h0, tid);
        sts_tile(buf[0], pre, tid);
    }
    __syncthreads();

    float gs = 0.f, gs2 = 0.f;
    int cur = 0;
    for (int cc = 0; cc < CPG_; ++cc) {
        // prefetch next channel
        float4 pre[5];
        const bool more = (cc + 1) < CPG_;
        if (more) ldg_tile(pre, x4 + plane0 + (size_t)(cc+1)*HWQ, h0, tid);

        float wk[9];
        #pragma unroll
        for (int k = 0; k < 9; ++k) wk[k] = wsm[k][cc];

        const float* tile = (const float*)buf[cur];
        float L0 = hasL ? tile[tid-1]    : 0.f;
        float M0 =        tile[tid];
        float R0 = hasR ? tile[tid+1]    : 0.f;
        float L1 = hasL ? tile[W_+tid-1] : 0.f;
        float M1 =        tile[W_+tid];
        float R1 = hasR ? tile[W_+tid+1] : 0.f;
        #pragma unroll
        for (int r = 0; r < ROWS; ++r) {
            const float* row2 = tile + (r+2)*W_;
            const float L2 = hasL ? row2[tid-1] : 0.f;
            const float M2 =        row2[tid];
            const float R2 = hasR ? row2[tid+1] : 0.f;
            float conv =        L0*wk[0];
            conv = fmaf(M0, wk[1], conv); conv = fmaf(R0, wk[2], conv);
            conv = fmaf(L1, wk[3], conv); conv = fmaf(M1, wk[4], conv);
            conv = fmaf(R1, wk[5], conv); conv = fmaf(L2, wk[6], conv);
            conv = fmaf(M2, wk[7], conv); conv = fmaf(R2, wk[8], conv);
            gs  += conv;
            gs2  = fmaf(conv, conv, gs2);
            L0=L1; M0=M1; R0=R1; L1=L2; M1=M2; R1=R2;
        }

        if (more) sts_tile(buf[cur^1], pre, tid);
        __syncthreads();
        cur ^= 1;
    }

    #pragma unroll
    for (int off = 16; off; off >>= 1) {
        gs  += __shfl_down_sync(0xffffffffu, gs,  off);
        gs2 += __shfl_down_sync(0xffffffffu, gs2, off);
    }
    if (lane == 0) { red[wid] = gs; red2[wid] = gs2; }
    __syncthreads();
    if (wid == 0) {
        float s  = (lane < 8) ? red[lane]  : 0.f;
        float s2 = (lane < 8) ? red2[lane] : 0.f;
        #pragma unroll
        for (int off = 4; off; off >>= 1) {
            s  += __shfl_down_sync(0xffffffffu, s,  off);
            s2 += __shfl_down_sync(0xffffffffu, s2, off);
        }
        if (lane == 0) {
            const int idx = ((n*G_ + g)*CHUNKS + chunk)*2;
            g_part[idx]   = s;
            g_part[idx+1] = s2;
        }
    }
}

// ---------------- Tiny reduce: partials -> mean, rstd ----------------
__global__ void k_reduce() {
    const int t = threadIdx.x;                      // 0..63 = n*G + g
    if (t < N_*G_) {
        float s = 0.f, s2 = 0.f;
        #pragma unroll
        for (int k = 0; k < CHUNKS; ++k) {
            s  += g_part[(t*CHUNKS + k)*2];
            s2 += g_part[(t*CHUNKS + k)*2 + 1];
        }
        const float inv = 1.0f / (float)(CPG_*H_*W_);
        const float m = s * inv;
        const float v = s2 * inv - m*m;
        g_stats[t*2]   = m;
        g_stats[t*2+1] = rsqrtf(v + EPS_);
    }
}

// ---------------- Pass 2a: conv recompute + norm/act/residual + group exp-sum ----------------
// Blocks + channels walked in REVERSE of pass1's order so pass2a's reads start
// on the tail of x, which pass1 left resident in L2 (x=134MB vs L2=126MB).
__global__ __launch_bounds__(NT) void k_pass2a(const float* __restrict__ x,
                                               const float* __restrict__ wgt) {
    __shared__ float4 buf[2][TQ];
    __shared__ float  wsm[9][CPG_];

    const int bid   = (gridDim.x - 1) - blockIdx.x;   // reversed
    const int chunk = bid % CHUNKS;
    const int g     = (bid / CHUNKS) % G_;
    const int n     = bid / (CHUNKS * G_);
    const int h0    = chunk * ROWS;
    const int tid   = threadIdx.x;
    const bool hasL = tid > 0, hasR = tid < W_-1;

    if (tid < 9*CPG_) {
        const int k = tid / CPG_, cc = tid % CPG_;
        wsm[k][cc] = wgt[k*C_ + g*CPG_ + cc];
    }
    const float mean = g_stats[(n*G_ + g)*2];
    const float rstd = g_stats[(n*G_ + g)*2 + 1];

    const float4* x4 = (const float4*)x;
    const size_t plane0 = (size_t)(n*C_ + g*CPG_) * HWQ;

    // prologue: channel CPG_-1 first (reverse order)
    {
        float4 pre[5];
        ldg_tile(pre, x4 + plane0 + (size_t)(CPG_-1)*HWQ, h0, tid);
        sts_tile(buf[0], pre, tid);
    }
    __syncthreads();

    float acc[ROWS];
    #pragma unroll
    for (int r = 0; r < ROWS; ++r) acc[r] = 0.f;

    int cur = 0;
    for (int i = 0; i < CPG_; ++i) {
        const int cc = CPG_ - 1 - i;                 // descending channel
        float4 pre[5];
        const bool more = (i + 1) < CPG_;
        if (more) ldg_tile(pre, x4 + plane0 + (size_t)(cc-1)*HWQ, h0, tid);

        float wk[9];
        #pragma unroll
        for (int k = 0; k < 9; ++k) wk[k] = wsm[k][cc];

        const float* tile = (const float*)buf[cur];
        float L0 = hasL ? tile[tid-1]    : 0.f;
        float M0 =        tile[tid];
        float R0 = hasR ? tile[tid+1]    : 0.f;
        float L1 = hasL ? tile[W_+tid-1] : 0.f;
        float M1 =        tile[W_+tid];
        float R1 = hasR ? tile[W_+tid+1] : 0.f;
        #pragma unroll
        for (int r = 0; r < ROWS; ++r) {
            const float* row2 = tile + (r+2)*W_;
            const float L2 = hasL ? row2[tid-1] : 0.f;
            const float M2 =        row2[tid];
            const float R2 = hasR ? row2[tid+1] : 0.f;
            float conv =        L0*wk[0];
            conv = fmaf(M0, wk[1], conv); conv = fmaf(R0, wk[2], conv);
            conv = fmaf(L1, wk[3], conv); conv = fmaf(M1, wk[4], conv);
            conv = fmaf(R1, wk[5], conv); conv = fmaf(L2, wk[6], conv);
            conv = fmaf(M2, wk[7], conv); conv = fmaf(R2, wk[8], conv);
            const float v = (conv - mean) * rstd;
            const float t = tanh_fast(v);
            // t in (-1,1) => clip(t+3,0,6) == t+3 exactly
            const float xr = fmaf(t * (1.0f/6.0f), t + 3.0f, conv);
            acc[r] += __expf(xr);
            L0=L1; M0=M1; R0=R1; L1=L2; M1=M2; R1=R2;
        }

        if (more) sts_tile(buf[cur^1], pre, tid);
        __syncthreads();
        cur ^= 1;
    }

    float* es = g_esum + ((size_t)(n*G_ + g)*H_ + h0) * W_;
    #pragma unroll
    for (int r = 0; r < ROWS; ++r) es[r*W_ + tid] = acc[r];
}

// ---------------- Pass 2b: combine groups, log, broadcast 16 channels/block ----------------
__global__ __launch_bounds__(NT) void k_pass2b(float* __restrict__ out) {
    const int p   = blockIdx.x * NT + threadIdx.x;  // quad index
    const int n   = p >> 14;                        // / HWQ
    const int pix = p & (HWQ - 1);
    const int c0  = blockIdx.y * CHPB;

    const float4* e4 = (const float4*)g_esum;
    const size_t ebase = (size_t)n*G_*HWQ + pix;
    float4 s = __ldg(&e4[ebase]);
    #pragma unroll
    for (int g = 1; g < G_; ++g) {
        const float4 v = __ldg(&e4[ebase + (size_t)g*HWQ]);
        s.x += v.x; s.y += v.y; s.z += v.z; s.w += v.w;
    }
    float4 L;
    L.x = __logf(s.x); L.y = __logf(s.y); L.z = __logf(s.z); L.w = __logf(s.w);

    float4* o4 = (float4*)out;
    const size_t obase = (size_t)n*C_*HWQ + (size_t)c0*HWQ + pix;
    #pragma unroll
    for (int c = 0; c < CHPB; ++c) __stcs(&o4[obase + (size_t)c*HWQ], L);
}

extern "C" void kernel_launch(void* const* d_in, const int* in_sizes, int n_in,
                              void* d_out, int out_size) {
    const float* x   = (const float*)d_in[0];       // [8,64,256,256]
    const float* wgt = (const float*)d_in[1];       // [3,3,64]
    float* out = (float*)d_out;

    k_pass1 <<<N_*G_*CHUNKS, NT>>>(x, wgt);
    k_reduce<<<1, 64>>>();
    k_pass2a<<<N_*G_*CHUNKS, NT>>>(x, wgt);
    k_pass2b<<<dim3((N_*HWQ)/NT, CSPLIT), NT>>>(out);
}

// round 5
// speedup vs baseline: 2.2123x; 1.0422x over previous
#include <cuda_runtime.h>
#include <cstdint>

#define N_   8
#define C_   64
#define H_   256
#define W_   256
#define G_   8
#define CPG_ 8               // channels per group
#define ROWS 8               // rows per block strip
#define TR   (ROWS+2)        // tile rows incl. halo
#define CHUNKS (H_/ROWS)     // 32
#define EPS_ 1e-5f
#define NT   256
#define W4_  (W_/4)          // 64
#define TQ   (TR*W4_)        // 640 float4 per tile
#define HWQ  (H_*W_/4)       // 16384 quads per plane
#define CSPLIT 8             // channel split in pass2b
#define CHPB (C_/CSPLIT)     // 8 channels per pass2b block

// Static scratch (no runtime allocation)
__device__ float g_part[N_*G_*CHUNKS*2];
__device__ float g_stats[N_*G_*2];                 // mean, rstd interleaved
__device__ float g_esum[(size_t)N_*G_*H_*W_];      // per-(n,g) sum of exp (16.8 MB)

__device__ __forceinline__ float tanh_fast(float x) {
    float y;
    asm("tanh.approx.f32 %0, %1;" : "=f"(y) : "f"(x));
    return y;
}

#define CP_COMMIT() asm volatile("cp.async.commit_group;")
#define CP_WAIT1()  asm volatile("cp.async.wait_group 1;")

// Stage one (TR x W_) channel tile gmem -> smem via cp.async.cg (no regs, no STS).
// Out-of-range rows zero-fill via src-size=0.
__device__ __forceinline__ void cpa_tile(unsigned sbase, const float4* __restrict__ xc4,
                                         int h0, int tid) {
    #pragma unroll
    for (int i = 0; i < 3; ++i) {
        const int idx = tid + i*NT;
        if (idx < TQ) {
            const int r = idx >> 6, q = idx & (W4_-1);
            const int h = h0 - 1 + r;
            const bool v = (h >= 0) && (h < H_);
            const float4* src = xc4 + (v ? (h*W4_ + q) : q);   // clamped (unread if sz=0)
            const int sz = v ? 16 : 0;
            asm volatile("cp.async.cg.shared.global [%0], [%1], 16, %2;"
                         :: "r"(sbase + (unsigned)idx*16u), "l"(src), "r"(sz));
        }
    }
}

// 3x3 depthwise conv over the strip for this thread's column; calls SINK(r, conv).
#define CONV_STRIP(tile, wk, SINK)                                        \
    {                                                                     \
        float L0 = hasL ? (tile)[tid-1]    : 0.f;                         \
        float M0 =        (tile)[tid];                                    \
        float R0 = hasR ? (tile)[tid+1]    : 0.f;                         \
        float L1 = hasL ? (tile)[W_+tid-1] : 0.f;                         \
        float M1 =        (tile)[W_+tid];                                 \
        float R1 = hasR ? (tile)[W_+tid+1] : 0.f;                         \
        _Pragma("unroll")                                                 \
        for (int r = 0; r < ROWS; ++r) {                                  \
            const float* row2 = (tile) + (r+2)*W_;                        \
            const float L2 = hasL ? row2[tid-1] : 0.f;                    \
            const float M2 =        row2[tid];                            \
            const float R2 = hasR ? row2[tid+1] : 0.f;                    \
            float conv =        L0*wk[0];                                 \
            conv = fmaf(M0, wk[1], conv); conv = fmaf(R0, wk[2], conv);   \
            conv = fmaf(L1, wk[3], conv); conv = fmaf(M1, wk[4], conv);   \
            conv = fmaf(R1, wk[5], conv); conv = fmaf(L2, wk[6], conv);   \
            conv = fmaf(M2, wk[7], conv); conv = fmaf(R2, wk[8], conv);   \
            SINK;                                                         \
            L0=L1; M0=M1; R0=R1; L1=L2; M1=M2; R1=R2;                     \
        }                                                                 \
    }

// ---------------- Pass 1: depthwise conv + per-(n,g,chunk) sum / sumsq ----------------
__global__ __launch_bounds__(NT) void k_pass1(const float* __restrict__ x,
                                              const float* __restrict__ wgt) {
    __shared__ float4 buf[3][TQ];                   // 30.7 KB triple buffer
    __shared__ float  wsm[9][CPG_];
    __shared__ float  red[8], red2[8];

    const int bid   = blockIdx.x;
    const int chunk = bid % CHUNKS;
    const int g     = (bid / CHUNKS) % G_;
    const int n     = bid / (CHUNKS * G_);
    const int h0    = chunk * ROWS;
    const int tid   = threadIdx.x;
    const int lane  = tid & 31, wid = tid >> 5;
    const bool hasL = tid > 0, hasR = tid < W_-1;

    if (tid < 9*CPG_) {
        const int k = tid / CPG_, cc = tid % CPG_;
        wsm[k][cc] = wgt[k*C_ + g*CPG_ + cc];
    }

    const unsigned sb0 = (unsigned)__cvta_generic_to_shared(&buf[0][0]);
    const unsigned sb1 = (unsigned)__cvta_generic_to_shared(&buf[1][0]);
    const unsigned sb2 = (unsigned)__cvta_generic_to_shared(&buf[2][0]);

    const float4* x4 = (const float4*)x;
    const size_t plane0 = (size_t)(n*C_ + g*CPG_) * HWQ;

    // prologue: channels 0, 1 in flight
    cpa_tile(sb0, x4 + plane0,       h0, tid); CP_COMMIT();
    cpa_tile(sb1, x4 + plane0 + HWQ, h0, tid); CP_COMMIT();

    float gs = 0.f, gs2 = 0.f;
    int bsel = 0;
    for (int cc = 0; cc < CPG_; ++cc) {
        CP_WAIT1();                                 // channel cc resident
        __syncthreads();
        if (cc + 2 < CPG_) {                        // stream channel cc+2 into retired buffer
            const unsigned sb = (bsel == 0) ? sb2 : (bsel == 1) ? sb0 : sb1;
            cpa_tile(sb, x4 + plane0 + (size_t)(cc+2)*HWQ, h0, tid);
        }
        CP_COMMIT();                                // (empty group at tail keeps WAIT1 valid)

        float wk[9];
        #pragma unroll
        for (int k = 0; k < 9; ++k) wk[k] = wsm[k][cc];
        const float* tile = (const float*)buf[bsel];
        CONV_STRIP(tile, wk, { gs += conv; gs2 = fmaf(conv, conv, gs2); });
        bsel = (bsel + 1 == 3) ? 0 : bsel + 1;
    }

    #pragma unroll
    for (int off = 16; off; off >>= 1) {
        gs  += __shfl_down_sync(0xffffffffu, gs,  off);
        gs2 += __shfl_down_sync(0xffffffffu, gs2, off);
    }
    if (lane == 0) { red[wid] = gs; red2[wid] = gs2; }
    __syncthreads();
    if (wid == 0) {
        float s  = (lane < 8) ? red[lane]  : 0.f;
        float s2 = (lane < 8) ? red2[lane] : 0.f;
        #pragma unroll
        for (int off = 4; off; off >>= 1) {
            s  += __shfl_down_sync(0xffffffffu, s,  off);
            s2 += __shfl_down_sync(0xffffffffu, s2, off);
        }
        if (lane == 0) {
            const int idx = ((n*G_ + g)*CHUNKS + chunk)*2;
            g_part[idx]   = s;
            g_part[idx+1] = s2;
        }
    }
}

// ---------------- Tiny reduce: partials -> mean, rstd ----------------
__global__ void k_reduce() {
    const int t = threadIdx.x;                      // 0..63 = n*G + g
    if (t < N_*G_) {
        float s = 0.f, s2 = 0.f;
        #pragma unroll
        for (int k = 0; k < CHUNKS; ++k) {
            s  += g_part[(t*CHUNKS + k)*2];
            s2 += g_part[(t*CHUNKS + k)*2 + 1];
        }
        const float inv = 1.0f / (float)(CPG_*H_*W_);
        const float m = s * inv;
        const float v = s2 * inv - m*m;
        g_stats[t*2]   = m;
        g_stats[t*2+1] = rsqrtf(v + EPS_);
    }
}

// ---------------- Pass 2a: conv recompute + norm/act/residual + group exp-sum ----------------
// Blocks + channels reversed vs pass1 so reads start on the L2-resident tail of x.
__global__ __launch_bounds__(NT) void k_pass2a(const float* __restrict__ x,
                                               const float* __restrict__ wgt) {
    __shared__ float4 buf[3][TQ];
    __shared__ float  wsm[9][CPG_];

    const int bid   = (gridDim.x - 1) - blockIdx.x;   // reversed
    const int chunk = bid % CHUNKS;
    const int g     = (bid / CHUNKS) % G_;
    const int n     = bid / (CHUNKS * G_);
    const int h0    = chunk * ROWS;
    const int tid   = threadIdx.x;
    const bool hasL = tid > 0, hasR = tid < W_-1;

    if (tid < 9*CPG_) {
        const int k = tid / CPG_, cc = tid % CPG_;
        wsm[k][cc] = wgt[k*C_ + g*CPG_ + cc];
    }
    const float mean = g_stats[(n*G_ + g)*2];
    const float rstd = g_stats[(n*G_ + g)*2 + 1];

    const unsigned sb0 = (unsigned)__cvta_generic_to_shared(&buf[0][0]);
    const unsigned sb1 = (unsigned)__cvta_generic_to_shared(&buf[1][0]);
    const unsigned sb2 = (unsigned)__cvta_generic_to_shared(&buf[2][0]);

    const float4* x4 = (const float4*)x;
    const size_t plane0 = (size_t)(n*C_ + g*CPG_) * HWQ;

    // prologue (descending channels): 7, 6 in flight
    cpa_tile(sb0, x4 + plane0 + (size_t)(CPG_-1)*HWQ, h0, tid); CP_COMMIT();
    cpa_tile(sb1, x4 + plane0 + (size_t)(CPG_-2)*HWQ, h0, tid); CP_COMMIT();

    float acc[ROWS];
    #pragma unroll
    for (int r = 0; r < ROWS; ++r) acc[r] = 0.f;

    int bsel = 0;
    for (int i = 0; i < CPG_; ++i) {
        const int cc = CPG_ - 1 - i;
        CP_WAIT1();
        __syncthreads();
        if (i + 2 < CPG_) {
            const unsigned sb = (bsel == 0) ? sb2 : (bsel == 1) ? sb0 : sb1;
            cpa_tile(sb, x4 + plane0 + (size_t)(cc-2)*HWQ, h0, tid);
        }
        CP_COMMIT();

        float wk[9];
        #pragma unroll
        for (int k = 0; k < 9; ++k) wk[k] = wsm[k][cc];
        const float* tile = (const float*)buf[bsel];
        CONV_STRIP(tile, wk, {
            const float v = (conv - mean) * rstd;
            const float t = tanh_fast(v);
            // t in (-1,1) => clip(t+3,0,6) == t+3 exactly
            const float xr = fmaf(t * (1.0f/6.0f), t + 3.0f, conv);
            acc[r] += __expf(xr);
        });
        bsel = (bsel + 1 == 3) ? 0 : bsel + 1;
    }

    float* es = g_esum + ((size_t)(n*G_ + g)*H_ + h0) * W_;
    #pragma unroll
    for (int r = 0; r < ROWS; ++r) es[r*W_ + tid] = acc[r];
}

// ---------------- Pass 2b: combine groups, log, broadcast 8 channels/block ----------------
__global__ __launch_bounds__(NT) void k_pass2b(float* __restrict__ out) {
    const int p   = blockIdx.x * NT + threadIdx.x;  // quad index
    const int n   = p >> 14;                        // / HWQ
    const int pix = p & (HWQ - 1);
    const int c0  = blockIdx.y * CHPB;

    const float4* e4 = (const float4*)g_esum;
    const size_t ebase = (size_t)n*G_*HWQ + pix;
    float4 s = __ldg(&e4[ebase]);
    #pragma unroll
    for (int g = 1; g < G_; ++g) {
        const float4 v = __ldg(&e4[ebase + (size_t)g*HWQ]);
        s.x += v.x; s.y += v.y; s.z += v.z; s.w += v.w;
    }
    float4 L;
    L.x = __logf(s.x); L.y = __logf(s.y); L.z = __logf(s.z); L.w = __logf(s.w);

    float4* o4 = (float4*)out;
    const size_t obase = (size_t)n*C_*HWQ + (size_t)c0*HWQ + pix;
    #pragma unroll
    for (int c = 0; c < CHPB; ++c) __stcs(&o4[obase + (size_t)c*HWQ], L);
}

extern "C" void kernel_launch(void* const* d_in, const int* in_sizes, int n_in,
                              void* d_out, int out_size) {
    const float* x   = (const float*)d_in[0];       // [8,64,256,256]
    const float* wgt = (const float*)d_in[1];       // [3,3,64]
    float* out = (float*)d_out;

    k_pass1 <<<N_*G_*CHUNKS, NT>>>(x, wgt);
    k_reduce<<<1, 64>>>();
    k_pass2a<<<N_*G_*CHUNKS, NT>>>(x, wgt);
    k_pass2b<<<dim3((N_*HWQ)/NT, CSPLIT), NT>>>(out);
}